// round 5
// baseline (speedup 1.0000x reference)
#include <cuda_runtime.h>
#include <cstdint>

// ---------------------------------------------------------------------------
// PoincareEmbeddings: out[b,l,:] = custom ? T[cm] : Rw[rm] + lin_b
// where T[k] = lin_w @ mobius_add(logmap0(custom_fixed_w[k]), custom_train_w[k]) + lin_b
//
// Two independent chains, overlapped on two streams:
//   side: mobius -> wprep -> gemm            (builds g_T; latency/tensor bound)
//   main: ptab -> gather_regular             (80% of output rows; HBM bound)
//   join: gather_custom                      (remaining rows from g_T)
// ---------------------------------------------------------------------------

constexpr int P_    = 300;
constexpr int PPAD  = 320;
constexpr int E_    = 256;
constexpr int Kc    = 20000;
constexpr int KP1   = Kc + 1;
constexpr int KROWS = 20096;
constexpr int VMAX  = 100000;

__device__ float g_M[(size_t)KROWS * PPAD];
__device__ float g_T[(size_t)KROWS * E_];
__device__ float g_Wp[(size_t)E_ * PPAD];
__device__ unsigned long long g_ptr[VMAX];   // row pointer | custom-flag (bit0)

__device__ __forceinline__ float tf32_rna(float x) {
    float r;
    asm("cvt.rna.tf32.f32 %0, %1;" : "=f"(r) : "f"(x));
    return r;
}

// ---------------------------------------------------------------------------
// Kernel 1: per custom row k: M[k] = tf32(mobius_add(logmap0(fixed[k]), train[k]))
// ---------------------------------------------------------------------------
__global__ void __launch_bounds__(256) k_mobius(const float* __restrict__ fixed_w,
                                                const float* __restrict__ train_w) {
    int warp = (blockIdx.x * blockDim.x + threadIdx.x) >> 5;
    int lane = threadIdx.x & 31;
    if (warp >= KROWS) return;
    float* Mrow = g_M + (size_t)warp * PPAD;

    if (warp >= KP1) {
        for (int p = lane; p < PPAD; p += 32) Mrow[p] = 0.0f;
        return;
    }

    const float* f = fixed_w + (size_t)warp * P_;
    const float* t = train_w + (size_t)warp * P_;

    float fr[10], tr[10];
    float sf2 = 0.f, sft = 0.f, st2 = 0.f;
#pragma unroll
    for (int i = 0; i < 10; i++) {
        int p = lane + i * 32;
        float fv = (p < P_) ? __ldg(f + p) : 0.f;
        float tv = (p < P_) ? __ldg(t + p) : 0.f;
        fr[i] = fv; tr[i] = tv;
        sf2 += fv * fv;
        sft += fv * tv;
        st2 += tv * tv;
    }
#pragma unroll
    for (int off = 16; off; off >>= 1) {
        sf2 += __shfl_xor_sync(0xFFFFFFFFu, sf2, off);
        sft += __shfl_xor_sync(0xFFFFFFFFu, sft, off);
        st2 += __shfl_xor_sync(0xFFFFFFFFu, st2, off);
    }

    float norm  = sqrtf(sf2);
    float scale = (norm > 0.f) ? (atanhf(norm) / norm) : 1.0f;

    float x2 = scale * scale * sf2;
    float xy = scale * sft;
    float y2 = st2;
    float cu = 1.f + 2.f * xy + y2;
    float ct = 1.f - x2;
    float denom = fmaxf(1.f + 2.f * xy + x2 * y2, 1e-15f);
    float inv = 1.f / denom;

#pragma unroll
    for (int i = 0; i < 10; i++) {
        int p = lane + i * 32;
        float val = (p < P_) ? (cu * (scale * fr[i]) + ct * tr[i]) * inv : 0.f;
        Mrow[p] = tf32_rna(val);
    }
}

// ---------------------------------------------------------------------------
// Prep A: tf32-round + zero-pad lin_w into g_Wp [E][PPAD]
// ---------------------------------------------------------------------------
__global__ void __launch_bounds__(256) k_wprep(const float* __restrict__ W) {
    int idx = blockIdx.x * 256 + threadIdx.x;
    if (idx >= E_ * PPAD) return;
    int e = idx / PPAD, p = idx - e * PPAD;
    g_Wp[idx] = (p < P_) ? tf32_rna(__ldg(W + (size_t)e * P_ + p)) : 0.f;
}

// ---------------------------------------------------------------------------
// Prep B: per-vocab fused row pointer (bit0 => custom row)
// ---------------------------------------------------------------------------
__global__ void __launch_bounds__(256) k_ptab(const int* __restrict__ v2c,
                                              const int* __restrict__ v2r,
                                              const float* __restrict__ Rw, int V) {
    int v = blockIdx.x * 256 + threadIdx.x;
    if (v >= V) return;
    int cm = __ldg(v2c + v);
    int rm = __ldg(v2r + v);
    unsigned long long p;
    if (cm) p = (unsigned long long)(g_T + (size_t)cm * E_) | 1ULL;
    else    p = (unsigned long long)(Rw  + (size_t)rm * E_);
    g_ptr[v] = p;
}

// ---------------------------------------------------------------------------
// Kernel 2: tf32 MMA GEMM  T[k,e] = sum_p M[k,p]*g_Wp[e,p] + lin_b[e]
// 128x64x32 block tile, 8 warps (4x2), warp 32x32, 2-stage cp.async.
// ---------------------------------------------------------------------------
constexpr int BM = 128, BN = 64, BK = 32;
constexpr int SPAD = BK + 4;
constexpr int A_ST = BM * SPAD;
constexpr int B_ST = BN * SPAD;
constexpr int SMEM_FLOATS = 2 * (A_ST + B_ST);
constexpr int NIT = PPAD / BK;

__device__ __forceinline__ void cpa16(uint32_t dst, const float* src) {
    asm volatile("cp.async.cg.shared.global [%0], [%1], 16;" :: "r"(dst), "l"(src));
}

__global__ void __launch_bounds__(256) k_gemm(const float* __restrict__ bias) {
    extern __shared__ float sm[];
    float* As[2] = { sm,            sm + A_ST };
    float* Bs[2] = { sm + 2 * A_ST, sm + 2 * A_ST + B_ST };

    int tid  = threadIdx.x;
    int warp = tid >> 5;
    int lane = tid & 31;
    int wm = warp >> 1;
    int wn = warp & 1;
    int rowBase = blockIdx.x * BM;
    int colBase = blockIdx.y * BN;
    int g  = lane >> 2;
    int tg = lane & 3;

    int ar[4], ac[4], br[2], bc[2];
#pragma unroll
    for (int i = 0; i < 4; i++) { int f4 = tid + i * 256; ar[i] = f4 >> 3; ac[i] = (f4 & 7) * 4; }
#pragma unroll
    for (int i = 0; i < 2; i++) { int f4 = tid + i * 256; br[i] = f4 >> 3; bc[i] = (f4 & 7) * 4; }

    auto load_tile = [&](int s, int p0) {
#pragma unroll
        for (int i = 0; i < 4; i++)
            cpa16((uint32_t)__cvta_generic_to_shared(As[s] + ar[i] * SPAD + ac[i]),
                  g_M + (size_t)(rowBase + ar[i]) * PPAD + p0 + ac[i]);
#pragma unroll
        for (int i = 0; i < 2; i++)
            cpa16((uint32_t)__cvta_generic_to_shared(Bs[s] + br[i] * SPAD + bc[i]),
                  g_Wp + (size_t)(colBase + br[i]) * PPAD + p0 + bc[i]);
    };

    float c[2][4][4];
#pragma unroll
    for (int mi = 0; mi < 2; mi++)
#pragma unroll
        for (int ni = 0; ni < 4; ni++)
#pragma unroll
            for (int r = 0; r < 4; r++) c[mi][ni][r] = 0.f;

    load_tile(0, 0);
    asm volatile("cp.async.commit_group;");

    for (int it = 0; it < NIT; it++) {
        int cur = it & 1;
        if (it + 1 < NIT) load_tile(cur ^ 1, (it + 1) * BK);
        asm volatile("cp.async.commit_group;");
        asm volatile("cp.async.wait_group 1;");
        __syncthreads();

        const float* Ac = As[cur];
        const float* Bc = Bs[cur];
#pragma unroll
        for (int kk = 0; kk < BK; kk += 8) {
            int k0 = kk + tg;
            uint32_t a[2][4];
#pragma unroll
            for (int mi = 0; mi < 2; mi++) {
                int r0 = wm * 32 + mi * 16 + g;
                a[mi][0] = __float_as_uint(Ac[r0 * SPAD + k0]);
                a[mi][1] = __float_as_uint(Ac[(r0 + 8) * SPAD + k0]);
                a[mi][2] = __float_as_uint(Ac[r0 * SPAD + k0 + 4]);
                a[mi][3] = __float_as_uint(Ac[(r0 + 8) * SPAD + k0 + 4]);
            }
            uint32_t b[4][2];
#pragma unroll
            for (int ni = 0; ni < 4; ni++) {
                int n0 = wn * 32 + ni * 8 + g;
                b[ni][0] = __float_as_uint(Bc[n0 * SPAD + k0]);
                b[ni][1] = __float_as_uint(Bc[n0 * SPAD + k0 + 4]);
            }
#pragma unroll
            for (int mi = 0; mi < 2; mi++)
#pragma unroll
                for (int ni = 0; ni < 4; ni++) {
                    asm volatile(
                        "mma.sync.aligned.m16n8k8.row.col.f32.tf32.tf32.f32 "
                        "{%0,%1,%2,%3}, {%4,%5,%6,%7}, {%8,%9}, {%0,%1,%2,%3};"
                        : "+f"(c[mi][ni][0]), "+f"(c[mi][ni][1]),
                          "+f"(c[mi][ni][2]), "+f"(c[mi][ni][3])
                        : "r"(a[mi][0]), "r"(a[mi][1]), "r"(a[mi][2]), "r"(a[mi][3]),
                          "r"(b[ni][0]), "r"(b[ni][1]));
                }
        }
        __syncthreads();
    }

#pragma unroll
    for (int mi = 0; mi < 2; mi++) {
#pragma unroll
        for (int ni = 0; ni < 4; ni++) {
            int col = colBase + wn * 32 + ni * 8 + tg * 2;
            float bx = __ldg(bias + col), by = __ldg(bias + col + 1);
            int r0 = rowBase + wm * 32 + mi * 16 + g;
            *(float2*)(g_T + (size_t)r0 * E_ + col) =
                make_float2(c[mi][ni][0] + bx, c[mi][ni][1] + by);
            *(float2*)(g_T + (size_t)(r0 + 8) * E_ + col) =
                make_float2(c[mi][ni][2] + bx, c[mi][ni][3] + by);
        }
    }
}

// ---------------------------------------------------------------------------
// Kernel 3a: regular tokens only (Rw row + lin_b). Custom warps exit early.
// 1 warp = 1 token, 2 float4 per lane, streaming stores.
// ---------------------------------------------------------------------------
__global__ void __launch_bounds__(256) k_gather_reg(const int* __restrict__ x,
                                                    const float* __restrict__ lin_b,
                                                    float4* __restrict__ out,
                                                    int ntok) {
    int gtid = blockIdx.x * 256 + threadIdx.x;
    int tok = gtid >> 5;
    int e4  = gtid & 31;
    if (tok >= ntok) return;

    int v = __ldg(x + tok);
    unsigned long long t = __ldg(g_ptr + v);
    if (t & 1ULL) return;                       // custom: handled in pass 2

    const float4* src = (const float4*)t;
    float4 a0 = __ldg(src + e4);
    float4 a1 = __ldg(src + e4 + 32);
    float4 b0 = __ldg((const float4*)lin_b + e4);
    float4 b1 = __ldg((const float4*)lin_b + e4 + 32);

    float4* dst = out + (size_t)tok * 64;
    __stcs(dst + e4,      make_float4(a0.x + b0.x, a0.y + b0.y, a0.z + b0.z, a0.w + b0.w));
    __stcs(dst + e4 + 32, make_float4(a1.x + b1.x, a1.y + b1.y, a1.z + b1.z, a1.w + b1.w));
}

// ---------------------------------------------------------------------------
// Kernel 3b: custom tokens only (g_T row, bias already folded).
// ---------------------------------------------------------------------------
__global__ void __launch_bounds__(256) k_gather_cus(const int* __restrict__ x,
                                                    float4* __restrict__ out,
                                                    int ntok) {
    int gtid = blockIdx.x * 256 + threadIdx.x;
    int tok = gtid >> 5;
    int e4  = gtid & 31;
    if (tok >= ntok) return;

    int v = __ldg(x + tok);
    unsigned long long t = __ldg(g_ptr + v);
    if (!(t & 1ULL)) return;                    // regular: already written

    const float4* src = (const float4*)(t & ~1ULL);
    float4 a0 = __ldg(src + e4);
    float4 a1 = __ldg(src + e4 + 32);

    float4* dst = out + (size_t)tok * 64;
    __stcs(dst + e4,      a0);
    __stcs(dst + e4 + 32, a1);
}

// ---------------------------------------------------------------------------
// Launch. Inputs: 0:x 1:custom_indices(unused) 2:v2c 3:v2r
//  4:custom_fixed_w 5:custom_train_w 6:regular_w 7:lin_w 8:lin_b
// ---------------------------------------------------------------------------
extern "C" void kernel_launch(void* const* d_in, const int* in_sizes, int n_in,
                              void* d_out, int out_size) {
    const int*   x    = (const int*)d_in[0];
    const int*   v2c  = (const int*)d_in[2];
    const int*   v2r  = (const int*)d_in[3];
    const float* fw   = (const float*)d_in[4];
    const float* tw   = (const float*)d_in[5];
    const float* Rw   = (const float*)d_in[6];
    const float* W    = (const float*)d_in[7];
    const float* bias = (const float*)d_in[8];
    float4* out = (float4*)d_out;

    int ntok = in_sizes[0];
    int V    = in_sizes[2];

    static cudaStream_t s_side = nullptr;
    static cudaEvent_t  ev_fork = nullptr, ev_join = nullptr;
    if (!s_side) {
        cudaFuncSetAttribute(k_gemm, cudaFuncAttributeMaxDynamicSharedMemorySize,
                             SMEM_FLOATS * (int)sizeof(float));
        cudaStreamCreateWithFlags(&s_side, cudaStreamNonBlocking);
        cudaEventCreateWithFlags(&ev_fork, cudaEventDisableTiming);
        cudaEventCreateWithFlags(&ev_join, cudaEventDisableTiming);
    }

    // fork: side stream = custom-table chain (no HBM pressure)
    cudaEventRecord(ev_fork, 0);
    cudaStreamWaitEvent(s_side, ev_fork, 0);

    k_mobius<<<KROWS / 8, 256, 0, s_side>>>(fw, tw);
    k_wprep<<<(E_ * PPAD + 255) / 256, 256, 0, s_side>>>(W);
    dim3 g2(KROWS / BM, E_ / BN);
    k_gemm<<<g2, 256, SMEM_FLOATS * sizeof(float), s_side>>>(bias);
    cudaEventRecord(ev_join, s_side);

    // main stream: regular-token chain (HBM bound), overlapped with the above
    k_ptab<<<(V + 255) / 256, 256>>>(v2c, v2r, Rw, V);
    int gthreads = ntok * 32;
    k_gather_reg<<<(gthreads + 255) / 256, 256>>>(x, bias, out, ntok);

    // join, then fill custom rows from g_T
    cudaStreamWaitEvent(0, ev_join, 0);
    k_gather_cus<<<(gthreads + 255) / 256, 256>>>(x, out, ntok);
}